// round 11
// baseline (speedup 1.0000x reference)
#include <cuda_runtime.h>
#include <math.h>

// Batched SIREN MLP: coords (B,N,2) f32, flat_weights (B,921) f32 -> (B,N,1) f32
// 2->20->20->20->1, hidden act sin(20*(Wx+b)), final clip [0,1].
//
// Numerics contract (R4-R10 evidence):
//  - dots: UNCONTRACTED scalar round(mul)+round(add), k ascending, acc from 0
//    (FMA contraction fails; packed f32x2 fails — scalar FMUL/FADD only)
//  - +b, *20 separate rounded ops
//  - sine: abs err ~2e-8 class is sufficient (empirical layer-1 amplification
//    ~500x; R6/R7/R10 all land ~7.5-7.8e-4)
//
// R11: (1) 2 points/thread — every weight LDS feeds two points (halves LDS/pt,
// doubles ILP); (2) leaner sine — magic-add range reduction (no FRND/F2I on
// the cvt pipe; quadrant identity holds for any k) and 2-step Cody-Waite
// (dropped P3: residual ~1e-12 << budget).

#define HID 20
#define PSZ 921

// Branch-free sine, |x| <= ~1e5 safe (|k| < 2^21). Abs err ~2-3e-8.
__device__ __forceinline__ float sin_fast(float x) {
    constexpr float  INV_PIO2 = 0.63661977236758134308f;
    constexpr float  MAGIC = 12582912.0f;  // 1.5 * 2^23
    constexpr double PIO2 = 1.5707963267948966192313216916398;
    constexpr float  P1 = (float)PIO2;
    constexpr float  P2 = (float)(PIO2 - (double)P1);

    float t = fmaf(x, INV_PIO2, MAGIC);
    unsigned q = __float_as_uint(t);        // low 2 bits == k mod 4
    float kf = t - MAGIC;

    float r = fmaf(-kf, P1, x);
    r = fmaf(-kf, P2, r);

    float z = r * r;

    float p = fmaf(z,  2.75573192239858907e-6f, -1.98412698412698413e-4f);
    p = fmaf(z, p,  8.33333333333333322e-3f);
    p = fmaf(z, p, -1.66666666666666667e-1f);
    float sinv = fmaf(r * z, p, r);

    float c = fmaf(z, -2.75573192239858907e-7f, 2.48015873015873016e-5f);
    c = fmaf(z, c, -1.38888888888888889e-3f);
    c = fmaf(z, c,  4.16666666666666644e-2f);
    c = fmaf(z, c, -0.5f);
    float cosv = fmaf(z, c, 1.0f);

    float v = (q & 1u) ? cosv : sinv;
    return __uint_as_float(__float_as_uint(v) ^ ((q & 2u) << 30));
}

__global__ __launch_bounds__(256, 2) void siren_kernel(
    const float* __restrict__ coords,
    const float* __restrict__ weights,
    float* __restrict__ out,
    int N)
{
    __shared__ __align__(16) float s[PSZ];
    const int b = blockIdx.y;

    const float* wb = weights + (size_t)b * PSZ;
    for (int i = threadIdx.x; i < PSZ; i += blockDim.x) s[i] = wb[i];
    __syncthreads();

    const int n0 = blockIdx.x * 512 + threadIdx.x;
    const int n1 = n0 + 256;
    if (n0 >= N) return;
    const bool has1 = (n1 < N);

    const float2* cb =
        reinterpret_cast<const float2*>(coords + (size_t)b * (size_t)N * 2);
    const float2 cA = cb[n0];
    const float2 cB = has1 ? cb[n1] : cA;

    float a0A[HID], a1A[HID];
    float a0B[HID], a1B[HID];

    // ---- Layer 1: 2 -> 20 ----
    #pragma unroll
    for (int o = 0; o < HID; o++) {
        float2 w = *reinterpret_cast<const float2*>(&s[2 * o]);
        float bias = s[40 + o];
        float aA = __fadd_rn(__fmul_rn(w.x, cA.x), __fmul_rn(w.y, cA.y));
        float aB = __fadd_rn(__fmul_rn(w.x, cB.x), __fmul_rn(w.y, cB.y));
        aA = __fadd_rn(aA, bias);
        aB = __fadd_rn(aB, bias);
        a0A[o] = sin_fast(__fmul_rn(20.0f, aA));
        a0B[o] = sin_fast(__fmul_rn(20.0f, aB));
    }

    // ---- Layer 2: 20 -> 20 ---- (LDS.128 rows shared by both points)
    #pragma unroll
    for (int o = 0; o < HID; o++) {
        const float4* wrow = reinterpret_cast<const float4*>(&s[60 + o * HID]);
        float aA = 0.0f, aB = 0.0f;
        #pragma unroll
        for (int v = 0; v < HID / 4; v++) {
            float4 w = wrow[v];
            aA = __fadd_rn(aA, __fmul_rn(w.x, a0A[4 * v + 0]));
            aB = __fadd_rn(aB, __fmul_rn(w.x, a0B[4 * v + 0]));
            aA = __fadd_rn(aA, __fmul_rn(w.y, a0A[4 * v + 1]));
            aB = __fadd_rn(aB, __fmul_rn(w.y, a0B[4 * v + 1]));
            aA = __fadd_rn(aA, __fmul_rn(w.z, a0A[4 * v + 2]));
            aB = __fadd_rn(aB, __fmul_rn(w.z, a0B[4 * v + 2]));
            aA = __fadd_rn(aA, __fmul_rn(w.w, a0A[4 * v + 3]));
            aB = __fadd_rn(aB, __fmul_rn(w.w, a0B[4 * v + 3]));
        }
        float bias = s[460 + o];
        aA = __fadd_rn(aA, bias);
        aB = __fadd_rn(aB, bias);
        a1A[o] = sin_fast(__fmul_rn(20.0f, aA));
        a1B[o] = sin_fast(__fmul_rn(20.0f, aB));
    }

    // ---- Layer 3: 20 -> 20 ----
    #pragma unroll
    for (int o = 0; o < HID; o++) {
        const float4* wrow = reinterpret_cast<const float4*>(&s[480 + o * HID]);
        float aA = 0.0f, aB = 0.0f;
        #pragma unroll
        for (int v = 0; v < HID / 4; v++) {
            float4 w = wrow[v];
            aA = __fadd_rn(aA, __fmul_rn(w.x, a1A[4 * v + 0]));
            aB = __fadd_rn(aB, __fmul_rn(w.x, a1B[4 * v + 0]));
            aA = __fadd_rn(aA, __fmul_rn(w.y, a1A[4 * v + 1]));
            aB = __fadd_rn(aB, __fmul_rn(w.y, a1B[4 * v + 1]));
            aA = __fadd_rn(aA, __fmul_rn(w.z, a1A[4 * v + 2]));
            aB = __fadd_rn(aB, __fmul_rn(w.z, a1B[4 * v + 2]));
            aA = __fadd_rn(aA, __fmul_rn(w.w, a1A[4 * v + 3]));
            aB = __fadd_rn(aB, __fmul_rn(w.w, a1B[4 * v + 3]));
        }
        float bias = s[880 + o];
        aA = __fadd_rn(aA, bias);
        aB = __fadd_rn(aB, bias);
        a0A[o] = sin_fast(__fmul_rn(20.0f, aA));
        a0B[o] = sin_fast(__fmul_rn(20.0f, aB));
    }

    // ---- Layer 4: 20 -> 1, clip ----
    {
        const float4* wrow = reinterpret_cast<const float4*>(&s[900]);
        float aA = 0.0f, aB = 0.0f;
        #pragma unroll
        for (int v = 0; v < HID / 4; v++) {
            float4 w = wrow[v];
            aA = __fadd_rn(aA, __fmul_rn(w.x, a0A[4 * v + 0]));
            aB = __fadd_rn(aB, __fmul_rn(w.x, a0B[4 * v + 0]));
            aA = __fadd_rn(aA, __fmul_rn(w.y, a0A[4 * v + 1]));
            aB = __fadd_rn(aB, __fmul_rn(w.y, a0B[4 * v + 1]));
            aA = __fadd_rn(aA, __fmul_rn(w.z, a0A[4 * v + 2]));
            aB = __fadd_rn(aB, __fmul_rn(w.z, a0B[4 * v + 2]));
            aA = __fadd_rn(aA, __fmul_rn(w.w, a0A[4 * v + 3]));
            aB = __fadd_rn(aB, __fmul_rn(w.w, a0B[4 * v + 3]));
        }
        float bias = s[920];
        aA = __fadd_rn(aA, bias);
        aB = __fadd_rn(aB, bias);
        float* ob = out + (size_t)b * (size_t)N;
        ob[n0] = fminf(fmaxf(aA, 0.0f), 1.0f);
        if (has1) ob[n1] = fminf(fmaxf(aB, 0.0f), 1.0f);
    }
}

extern "C" void kernel_launch(void* const* d_in, const int* in_sizes, int n_in,
                              void* d_out, int out_size) {
    const float* coords  = (const float*)d_in[0];   // (B, N, 2)
    const float* weights = (const float*)d_in[1];   // (B, 921)
    float* out = (float*)d_out;                     // (B, N, 1)

    const int B = in_sizes[1] / PSZ;
    const int N = in_sizes[0] / (2 * B);

    dim3 block(256);
    dim3 grid((N + 511) / 512, B);
    siren_kernel<<<grid, block>>>(coords, weights, out, N);
}

// round 12
// speedup vs baseline: 1.1260x; 1.1260x over previous
#include <cuda_runtime.h>
#include <math.h>

// Batched SIREN MLP: coords (B,N,2) f32, flat_weights (B,921) f32 -> (B,N,1) f32
// 2->20->20->20->1, hidden act sin(20*(Wx+b)), final clip [0,1].
//
// Numerics contract (R4-R11 evidence):
//  - dots: UNCONTRACTED scalar round(mul)+round(add), k ascending, acc from 0
//    (FMA contraction fails; packed f32x2 fails — scalar FMUL/FADD only)
//  - +b, *20 separate rounded ops
//  - sine: magic-add Cody-Waite-2 + Taylor (abs err ~2e-8) — validated R11
//    at rel_err 7.716e-4
//
// R12 = R10's occupancy shape (1 pt/thread, 256/block, ~64 regs, occ ~49%)
//       + R11's lean sine. R11's 2-pt/thread is reverted: 122 regs halved
//       occupancy (24.5%) and issue (71.7%) — a net loss.

#define HID 20
#define PSZ 921

// Branch-free sine, |x| <= ~1e5 safe (|k| < 2^21). Abs err ~2-3e-8.
__device__ __forceinline__ float sin_fast(float x) {
    constexpr float  INV_PIO2 = 0.63661977236758134308f;
    constexpr float  MAGIC = 12582912.0f;  // 1.5 * 2^23
    constexpr double PIO2 = 1.5707963267948966192313216916398;
    constexpr float  P1 = (float)PIO2;
    constexpr float  P2 = (float)(PIO2 - (double)P1);

    float t = fmaf(x, INV_PIO2, MAGIC);
    unsigned q = __float_as_uint(t);        // low 2 bits == k mod 4
    float kf = t - MAGIC;

    float r = fmaf(-kf, P1, x);
    r = fmaf(-kf, P2, r);

    float z = r * r;

    float p = fmaf(z,  2.75573192239858907e-6f, -1.98412698412698413e-4f);
    p = fmaf(z, p,  8.33333333333333322e-3f);
    p = fmaf(z, p, -1.66666666666666667e-1f);
    float sinv = fmaf(r * z, p, r);

    float c = fmaf(z, -2.75573192239858907e-7f, 2.48015873015873016e-5f);
    c = fmaf(z, c, -1.38888888888888889e-3f);
    c = fmaf(z, c,  4.16666666666666644e-2f);
    c = fmaf(z, c, -0.5f);
    float cosv = fmaf(z, c, 1.0f);

    float v = (q & 1u) ? cosv : sinv;
    return __uint_as_float(__float_as_uint(v) ^ ((q & 2u) << 30));
}

__global__ __launch_bounds__(256) void siren_kernel(
    const float* __restrict__ coords,
    const float* __restrict__ weights,
    float* __restrict__ out,
    int N)
{
    __shared__ __align__(16) float s[PSZ];
    const int b = blockIdx.y;

    const float* wb = weights + (size_t)b * PSZ;
    for (int i = threadIdx.x; i < PSZ; i += blockDim.x) s[i] = wb[i];
    __syncthreads();

    const int n = blockIdx.x * blockDim.x + threadIdx.x;
    if (n >= N) return;

    const float2 c =
        reinterpret_cast<const float2*>(coords + (size_t)b * (size_t)N * 2)[n];

    float a0[HID];
    float a1[HID];

    // ---- Layer 1: 2 -> 20 ---- (uncontracted; LDS.64 weight pairs)
    #pragma unroll
    for (int o = 0; o < HID; o++) {
        float2 w = *reinterpret_cast<const float2*>(&s[2 * o]);
        float acc = __fadd_rn(__fmul_rn(w.x, c.x), __fmul_rn(w.y, c.y));
        acc = __fadd_rn(acc, s[40 + o]);
        a0[o] = sin_fast(__fmul_rn(20.0f, acc));
    }

    // ---- Layer 2: 20 -> 20 ---- (sequential uncontracted; LDS.128 weights)
    #pragma unroll
    for (int o = 0; o < HID; o++) {
        const float4* wrow = reinterpret_cast<const float4*>(&s[60 + o * HID]);
        float acc = 0.0f;
        #pragma unroll
        for (int v = 0; v < HID / 4; v++) {
            float4 w = wrow[v];
            acc = __fadd_rn(acc, __fmul_rn(w.x, a0[4 * v + 0]));
            acc = __fadd_rn(acc, __fmul_rn(w.y, a0[4 * v + 1]));
            acc = __fadd_rn(acc, __fmul_rn(w.z, a0[4 * v + 2]));
            acc = __fadd_rn(acc, __fmul_rn(w.w, a0[4 * v + 3]));
        }
        acc = __fadd_rn(acc, s[460 + o]);
        a1[o] = sin_fast(__fmul_rn(20.0f, acc));
    }

    // ---- Layer 3: 20 -> 20 ----
    #pragma unroll
    for (int o = 0; o < HID; o++) {
        const float4* wrow = reinterpret_cast<const float4*>(&s[480 + o * HID]);
        float acc = 0.0f;
        #pragma unroll
        for (int v = 0; v < HID / 4; v++) {
            float4 w = wrow[v];
            acc = __fadd_rn(acc, __fmul_rn(w.x, a1[4 * v + 0]));
            acc = __fadd_rn(acc, __fmul_rn(w.y, a1[4 * v + 1]));
            acc = __fadd_rn(acc, __fmul_rn(w.z, a1[4 * v + 2]));
            acc = __fadd_rn(acc, __fmul_rn(w.w, a1[4 * v + 3]));
        }
        acc = __fadd_rn(acc, s[880 + o]);
        a0[o] = sin_fast(__fmul_rn(20.0f, acc));
    }

    // ---- Layer 4: 20 -> 1, clip ----
    {
        const float4* wrow = reinterpret_cast<const float4*>(&s[900]);
        float acc = 0.0f;
        #pragma unroll
        for (int v = 0; v < HID / 4; v++) {
            float4 w = wrow[v];
            acc = __fadd_rn(acc, __fmul_rn(w.x, a0[4 * v + 0]));
            acc = __fadd_rn(acc, __fmul_rn(w.y, a0[4 * v + 1]));
            acc = __fadd_rn(acc, __fmul_rn(w.z, a0[4 * v + 2]));
            acc = __fadd_rn(acc, __fmul_rn(w.w, a0[4 * v + 3]));
        }
        acc = __fadd_rn(acc, s[920]);
        out[(size_t)b * (size_t)N + n] = fminf(fmaxf(acc, 0.0f), 1.0f);
    }
}

extern "C" void kernel_launch(void* const* d_in, const int* in_sizes, int n_in,
                              void* d_out, int out_size) {
    const float* coords  = (const float*)d_in[0];   // (B, N, 2)
    const float* weights = (const float*)d_in[1];   // (B, 921)
    float* out = (float*)d_out;                     // (B, N, 1)

    const int B = in_sizes[1] / PSZ;
    const int N = in_sizes[0] / (2 * B);

    dim3 block(256);
    dim3 grid((N + 255) / 256, B);
    siren_kernel<<<grid, block>>>(coords, weights, out, N);
}